// round 7
// baseline (speedup 1.0000x reference)
#include <cuda_runtime.h>
#include <cuda_bf16.h>

#define H      488
#define AW     484          // H - 5 + 1
#define KCL    6
#define NB     32
#define ITERS  10
#define SEG    121          // 484 = 4 * 121 windows per row
#define NSEG   4
#define NPART  (AW * NSEG)  // 1936 partials per batch
#define CR0    8            // rows per scan0 chunk
#define NCH0   61           // ceil(484/8)
#define NE4    (H * H / 4)  // 59536 float4 per batch
#define RW     5            // warps per cluster in refine (30 of 32 warps)

// Scratch (allocation-free: __device__ globals)
__device__ float g_colsum[NB * AW * H];     // vertical 5-sums
__device__ float g_pv[NB * NPART];          // per-(row,seg) argmax value
__device__ int   g_pi[NB * NPART];          // per-(row,seg) argmax flat window idx

__device__ __forceinline__ void better(float v, int i, float& bv, int& bi) {
    if (v > bv || (v == bv && i < bi)) { bv = v; bi = i; }
}

// ---------------------------------------------------------------------------
// scan0: input -> colsum (global, float4) + initial argmax partials.
// grid (NB, 61) x 128. 8 rows per chunk, 4 cols per thread (vectorized).
// ---------------------------------------------------------------------------
__global__ __launch_bounds__(128)
void scan0_kernel(const float* __restrict__ in) {
    const int b = blockIdx.x, cb = blockIdx.y, tid = threadIdx.x;
    const float* src = in + (size_t)b * H * H;
    float* cs = g_colsum + (size_t)b * AW * H;

    __shared__ float s_cs[CR0][H];

    const int R0 = CR0 * cb, R1 = min(AW, R0 + CR0);

    // column 5-sums, 4 columns per thread via float4 (left-assoc per column)
    if (tid < H / 4) {
        const float4* s4 = (const float4*)src;
        float4* c4 = (float4*)cs;
        const int HQ = H / 4;                 // 122 float4 per row
        float4 w0 = s4[(R0 + 0) * HQ + tid], w1 = s4[(R0 + 1) * HQ + tid],
               w2 = s4[(R0 + 2) * HQ + tid], w3 = s4[(R0 + 3) * HQ + tid], w4;
        for (int i = R0; i < R1; i++) {
            w4 = s4[(i + 4) * HQ + tid];
            float4 s;
            s.x = w0.x + w1.x + w2.x + w3.x + w4.x;
            s.y = w0.y + w1.y + w2.y + w3.y + w4.y;
            s.z = w0.z + w1.z + w2.z + w3.z + w4.z;
            s.w = w0.w + w1.w + w2.w + w3.w + w4.w;
            *(float4*)&s_cs[i - R0][tid * 4] = s;
            c4[i * HQ + tid] = s;
            w0 = w1; w1 = w2; w2 = w3; w3 = w4;
        }
    }
    __syncthreads();

    // partials: up to 32 (row,seg) pairs, 4 sub-threads each
    const int pair = tid >> 2, sub = tid & 3;
    const int lr = pair >> 2, sg = pair & 3;
    const int nrows = R1 - R0;

    float bv = -1.0f; int bi = 0x7fffffff;
    if (lr < nrows) {
        const float* row = s_cs[lr];
        const int jbeg = sg * SEG;
        for (int j = jbeg + sub; j < jbeg + SEG; j += 4) {
            float v = row[j] + row[j + 1] + row[j + 2] + row[j + 3] + row[j + 4];
            better(v, (R0 + lr) * AW + j, bv, bi);
        }
    }
    #pragma unroll
    for (int off = 2; off; off >>= 1) {
        float ov = __shfl_down_sync(0xffffffffu, bv, off);
        int   oi = __shfl_down_sync(0xffffffffu, bi, off);
        better(ov, oi, bv, bi);
    }
    if (sub == 0 && lr < nrows) {
        g_pv[b * NPART + (R0 + lr) * NSEG + sg] = bv;
        g_pi[b * NPART + (R0 + lr) * NSEG + sg] = bi;
    }
}

// ---------------------------------------------------------------------------
// solve: one block per batch (1024 thr). Fused:
//   (I)   6 greedy extractions (smem partials, incremental colsum repair)
//   (II)  first-occurrence scan for all 6 window maxima (float max filter)
//   (III) 10 mean-shift iterations (5 warps/cluster; centers in smem,
//         updated by 6 threads; hot loop uses constant-index registers)
//   (IV)  round + clamped 4x4 confidence windows on the ORIGINAL heatmap
// ---------------------------------------------------------------------------
__global__ __launch_bounds__(1024)
void solve_kernel(const float* __restrict__ in, float* __restrict__ out) {
    const int b = blockIdx.x, tid = threadIdx.x;
    const int warp = tid >> 5, lane = tid & 31;
    const float* src = in + (size_t)b * H * H;
    float* cs = g_colsum + (size_t)b * AW * H;

    __shared__ float s_pv[NPART];
    __shared__ int   s_pi[NPART];
    __shared__ float s_rv[32];
    __shared__ int   s_ri[32];
    __shared__ float s_win[25];
    __shared__ int   s_wr[KCL], s_wc[KCL];
    __shared__ float s_mv[KCL];
    __shared__ int   s_r, s_c;
    __shared__ int   s_eq[KCL];
    __shared__ float s_cy[KCL], s_cx[KCL];
    __shared__ float pY[KCL][RW], pX[KCL][RW], pW[KCL][RW];

    for (int i = tid; i < NPART; i += 1024) {
        s_pv[i] = g_pv[b * NPART + i];
        s_pi[i] = g_pi[b * NPART + i];
    }
    if (tid < KCL) s_eq[tid] = 0x7fffffff;
    __syncthreads();

    // ==================== (I) greedy extractions ====================
    for (int it = 0; it < KCL; it++) {
        // A: argmax over 1936 smem partials (two-level shuffle tree)
        {
            float bv = -1.0f; int bi = 0x7fffffff;
            for (int i = tid; i < NPART; i += 1024) better(s_pv[i], s_pi[i], bv, bi);
            #pragma unroll
            for (int off = 16; off; off >>= 1) {
                float ov = __shfl_down_sync(0xffffffffu, bv, off);
                int   oi = __shfl_down_sync(0xffffffffu, bi, off);
                better(ov, oi, bv, bi);
            }
            if (lane == 0) { s_rv[warp] = bv; s_ri[warp] = bi; }
        }
        __syncthreads();
        if (warp == 0) {
            float bv = s_rv[lane]; int bi = s_ri[lane];
            #pragma unroll
            for (int off = 16; off; off >>= 1) {
                float ov = __shfl_down_sync(0xffffffffu, bv, off);
                int   oi = __shfl_down_sync(0xffffffffu, bi, off);
                better(ov, oi, bv, bi);
            }
            if (lane == 0) { s_r = bi / AW; s_c = bi % AW; }
        }
        __syncthreads();
        const int r = s_r, c = s_c;

        // B: window max (value = orig unless covered by window j < it)
        if (tid < 25) {
            int y = r + tid / 5, x = c + tid % 5;
            float v = src[y * H + x];
            for (int j = 0; j < it; j++)
                if ((unsigned)(y - s_wr[j]) < 5u && (unsigned)(x - s_wc[j]) < 5u) v = 0.0f;
            s_win[tid] = v;
        }
        __syncthreads();
        if (tid == 0) {
            float mv = -1.0f;
            #pragma unroll
            for (int i = 0; i < 25; i++) mv = fmaxf(mv, s_win[i]);
            s_mv[it] = mv; s_wr[it] = r; s_wc[it] = c;
        }

        // C: incremental colsum repair (<=45 entries), coverage j <= it
        const int r0c = max(0, r - 4), r1c = min(AW - 1, r + 4);
        {
            int nc = (r1c - r0c + 1) * 5;
            if (tid < nc) {
                int rr = r0c + tid / 5, cc = c + tid % 5;
                float s = 0.0f;
                #pragma unroll
                for (int d = 0; d < 5; d++) {
                    int y = rr + d;
                    float v = src[y * H + cc];
                    if ((unsigned)(y - r) < 5u && (unsigned)(cc - c) < 5u) v = 0.0f;
                    for (int j = 0; j < it; j++)
                        if ((unsigned)(y - s_wr[j]) < 5u && (unsigned)(cc - s_wc[j]) < 5u) v = 0.0f;
                    s = s + v;   // left-assoc, matches scan0 ring
                }
                cs[rr * H + cc] = s;
            }
        }
        __syncthreads();

        // D: recompute affected partials (<= 9 rows x <= 2 segs)
        {
            const int jlo = max(0, c - 4), jhi = min(AW - 1, c + 4);
            const int s0 = jlo / SEG, s1 = jhi / SEG;
            const int nsegs = s1 - s0 + 1;
            const int npairs = (r1c - r0c + 1) * nsegs;
            for (int p = warp; p < npairs; p += 32) {
                int rr = r0c + p / nsegs, sg = s0 + p % nsegs;
                const float* row = cs + rr * H;
                float bv2 = -1.0f; int bi2 = 0x7fffffff;
                for (int j = sg * SEG + lane; j < sg * SEG + SEG; j += 32) {
                    float v = row[j] + row[j + 1] + row[j + 2] + row[j + 3] + row[j + 4];
                    better(v, rr * AW + j, bv2, bi2);
                }
                #pragma unroll
                for (int off = 16; off; off >>= 1) {
                    float ov = __shfl_down_sync(0xffffffffu, bv2, off);
                    int   oi = __shfl_down_sync(0xffffffffu, bi2, off);
                    better(ov, oi, bv2, bi2);
                }
                if (lane == 0) { s_pv[rr * NSEG + sg] = bv2; s_pi[rr * NSEG + sg] = bi2; }
            }
        }
        __syncthreads();
    }

    // ==================== (II) first-occurrence eq scan ====================
    // Fast filter: max of 4 floats vs lo = min of the 6 window maxima
    // (uniform values -> slow path ~15%). Exact float equality vs the 6
    // maxima; coverage by earlier windows -> 0 (never equal). Shared
    // atomicMin (commutative -> deterministic).
    {
        float mv0 = s_mv[0], mv1 = s_mv[1], mv2 = s_mv[2],
              mv3 = s_mv[3], mv4 = s_mv[4], mv5 = s_mv[5];
        float lo = fminf(fminf(fminf(mv0, mv1), fminf(mv2, mv3)), fminf(mv4, mv5));
        const float4* h4 = (const float4*)src;
        for (int t4 = tid; t4 < NE4; t4 += 1024) {
            float4 v = h4[t4];
            float m4 = fmaxf(fmaxf(v.x, v.y), fmaxf(v.z, v.w));
            if (m4 < lo) continue;
            #pragma unroll
            for (int u = 0; u < 4; u++) {
                float val = (u == 0) ? v.x : (u == 1) ? v.y : (u == 2) ? v.z : v.w;
                int id = t4 * 4 + u;
                #pragma unroll
                for (int i = 0; i < KCL; i++) {
                    float mvi = (i == 0) ? mv0 : (i == 1) ? mv1 : (i == 2) ? mv2
                              : (i == 3) ? mv3 : (i == 4) ? mv4 : mv5;
                    if (val == mvi) {
                        int y = id / H, x = id - y * H;
                        bool cov = false;
                        for (int j = 0; j < i; j++)
                            if ((unsigned)(y - s_wr[j]) < 5u && (unsigned)(x - s_wc[j]) < 5u) cov = true;
                        if (!cov) atomicMin(&s_eq[i], id);
                    }
                }
            }
        }
    }
    __syncthreads();
    if (tid < KCL) {
        int fh = s_eq[tid];
        s_cy[tid] = (float)(fh / H);
        s_cx[tid] = (float)(fh % H);
    }
    __syncthreads();

    // ==================== (III) mean shift ====================
    const int k = warp / RW;            // 0..5 for warps 0..29; warps 30,31 idle
    const int sw = warp - k * RW;
    const bool active = (warp < KCL * RW);

    for (int it = 0; it < ITERS; it++) {
        // all 6 centers into registers (constant smem indices, no spill)
        float rcy[KCL], rcx[KCL];
        #pragma unroll
        for (int i = 0; i < KCL; i++) { rcy[i] = s_cy[i]; rcx[i] = s_cx[i]; }

        if (active) {
            float cy = rcy[0], cx = rcx[0];
            if (k == 1) { cy = rcy[1]; cx = rcx[1]; }
            if (k == 2) { cy = rcy[2]; cx = rcx[2]; }
            if (k == 3) { cy = rcy[3]; cx = rcx[3]; }
            if (k == 4) { cy = rcy[4]; cx = rcx[4]; }
            if (k == 5) { cy = rcy[5]; cx = rcx[5]; }

            const int y0 = max(0, (int)floorf(cy - 12.0f));
            const int y1 = min(H - 1, (int)ceilf(cy + 12.0f));
            const int x0 = max(0, (int)floorf(cx - 12.0f));
            const int x1 = min(H - 1, (int)ceilf(cx + 12.0f));
            const int w  = x1 - x0 + 1;        // <= 26 <= 32 lanes

            float sy = 0.0f, sx = 0.0f, swt = 0.0f;
            const int x = x0 + lane;
            if (lane < w) {
                const float fx = (float)x;
                const float dx = fx - cx;
                for (int y = y0 + sw; y <= y1; y += RW) {
                    float fy = (float)y;
                    float dy = fy - cy;
                    float d2 = fmaxf(dy * dy + dx * dx, 1e-6f);
                    if (d2 < 144.0f) {
                        float m2 = d2;
                        #pragma unroll
                        for (int k2 = 0; k2 < KCL; k2++) {
                            float ey = fy - rcy[k2], ex = fx - rcx[k2];
                            m2 = fminf(m2, fmaxf(ey * ey + ex * ex, 1e-6f));
                        }
                        float wgt = src[y * H + x] * sqrtf(m2) / d2;
                        sy += wgt * fy;
                        sx += wgt * fx;
                        swt += wgt;
                    }
                }
            }
            #pragma unroll
            for (int off = 16; off; off >>= 1) {
                sy  += __shfl_down_sync(0xffffffffu, sy, off);
                sx  += __shfl_down_sync(0xffffffffu, sx, off);
                swt += __shfl_down_sync(0xffffffffu, swt, off);
            }
            if (lane == 0) { pY[k][sw] = sy; pX[k][sw] = sx; pW[k][sw] = swt; }
        }
        __syncthreads();
        // 6 threads update centers (12 divides total, not 12k)
        if (tid < KCL) {
            float ay = pY[tid][0] + pY[tid][1] + pY[tid][2] + pY[tid][3] + pY[tid][4];
            float ax = pX[tid][0] + pX[tid][1] + pX[tid][2] + pX[tid][3] + pX[tid][4];
            float aw = pW[tid][0] + pW[tid][1] + pW[tid][2] + pW[tid][3] + pW[tid][4];
            s_cy[tid] = ay / aw;
            s_cx[tid] = ax / aw;
        }
        __syncthreads();
    }

    // ==================== (IV) outputs ====================
    if (tid < KCL) {
        float fy = s_cy[tid], fx = s_cx[tid];
        int iy = (int)rintf(fy);   // round-half-to-even == jnp.round
        int ix = (int)rintf(fx);
        out[(b * KCL + tid) * 2 + 0] = (float)iy;
        out[(b * KCL + tid) * 2 + 1] = (float)ix;
        int sy0 = min(max(iy - 2, 0), H - 4);   // dynamic_slice clamp
        int sx0 = min(max(ix - 2, 0), H - 4);
        float cf = 0.0f;
        #pragma unroll
        for (int di = 0; di < 4; di++)
            #pragma unroll
            for (int dj = 0; dj < 4; dj++)
                cf += src[(sy0 + di) * H + (sx0 + dj)];
        out[NB * KCL * 2 + b * KCL + tid] = cf;
    }
}

extern "C" void kernel_launch(void* const* d_in, const int* in_sizes, int n_in,
                              void* d_out, int out_size) {
    const float* hm = (const float*)d_in[0];
    float* out = (float*)d_out;

    scan0_kernel<<<dim3(NB, NCH0), 128>>>(hm);
    solve_kernel<<<NB, 1024>>>(hm, out);
}

// round 8
// speedup vs baseline: 1.2840x; 1.2840x over previous
#include <cuda_runtime.h>
#include <cuda_bf16.h>

#define H      488
#define AW     484          // H - 5 + 1
#define KCL    6
#define NB     32
#define ITERS  10
#define SEG    121          // 484 = 4 * 121 windows per row
#define NSEG   4
#define NPART  (AW * NSEG)  // 1936 partials per batch
#define CR0    8            // rows per scan0 chunk
#define NCH0   61           // ceil(484/8)
#define NE4    (H * H / 4)  // 59536 uint4/float4 per batch
#define NCHE   8            // eq chunks per batch
#define CE4    7442         // NE4 / 8
#define RW     5            // warps per cluster in refine (30 of 32 warps)

// Scratch (allocation-free: __device__ globals)
__device__ float g_colsum[NB * AW * H];     // vertical 5-sums
__device__ float g_pv[NB * NPART];          // per-(row,seg) argmax value
__device__ int   g_pi[NB * NPART];          // per-(row,seg) argmax flat window idx
__device__ int   g_wr[NB * KCL], g_wc[NB * KCL];
__device__ float g_mv[NB * KCL];
__device__ int   g_eq[NB * KCL];            // first-occurrence flat index

__device__ __forceinline__ void better(float v, int i, float& bv, int& bi) {
    if (v > bv || (v == bv && i < bi)) { bv = v; bi = i; }
}

// ---------------------------------------------------------------------------
// scan0: input -> colsum (global, float4) + initial argmax partials.
// grid (NB, 61) x 128. 8 rows per chunk, 4 cols per thread (vectorized).
// ---------------------------------------------------------------------------
__global__ __launch_bounds__(128)
void scan0_kernel(const float* __restrict__ in) {
    const int b = blockIdx.x, cb = blockIdx.y, tid = threadIdx.x;
    const float* src = in + (size_t)b * H * H;
    float* cs = g_colsum + (size_t)b * AW * H;

    __shared__ float s_cs[CR0][H];

    const int R0 = CR0 * cb, R1 = min(AW, R0 + CR0);

    // column 5-sums, 4 columns per thread via float4 (left-assoc per column)
    if (tid < H / 4) {
        const float4* s4 = (const float4*)src;
        float4* c4 = (float4*)cs;
        const int HQ = H / 4;                 // 122 float4 per row
        float4 w0 = s4[(R0 + 0) * HQ + tid], w1 = s4[(R0 + 1) * HQ + tid],
               w2 = s4[(R0 + 2) * HQ + tid], w3 = s4[(R0 + 3) * HQ + tid], w4;
        for (int i = R0; i < R1; i++) {
            w4 = s4[(i + 4) * HQ + tid];
            float4 s;
            s.x = w0.x + w1.x + w2.x + w3.x + w4.x;
            s.y = w0.y + w1.y + w2.y + w3.y + w4.y;
            s.z = w0.z + w1.z + w2.z + w3.z + w4.z;
            s.w = w0.w + w1.w + w2.w + w3.w + w4.w;
            *(float4*)&s_cs[i - R0][tid * 4] = s;
            c4[i * HQ + tid] = s;
            w0 = w1; w1 = w2; w2 = w3; w3 = w4;
        }
    }
    __syncthreads();

    // partials: up to 32 (row,seg) pairs, 4 sub-threads each
    const int pair = tid >> 2, sub = tid & 3;
    const int lr = pair >> 2, sg = pair & 3;
    const int nrows = R1 - R0;

    float bv = -1.0f; int bi = 0x7fffffff;
    if (lr < nrows) {
        const float* row = s_cs[lr];
        const int jbeg = sg * SEG;
        for (int j = jbeg + sub; j < jbeg + SEG; j += 4) {
            float v = row[j] + row[j + 1] + row[j + 2] + row[j + 3] + row[j + 4];
            better(v, (R0 + lr) * AW + j, bv, bi);
        }
    }
    #pragma unroll
    for (int off = 2; off; off >>= 1) {
        float ov = __shfl_down_sync(0xffffffffu, bv, off);
        int   oi = __shfl_down_sync(0xffffffffu, bi, off);
        better(ov, oi, bv, bi);
    }
    if (sub == 0 && lr < nrows) {
        g_pv[b * NPART + (R0 + lr) * NSEG + sg] = bv;
        g_pi[b * NPART + (R0 + lr) * NSEG + sg] = bi;
    }
}

// ---------------------------------------------------------------------------
// greedy6: 6 greedy extractions per batch. grid NB x 512.
// Partials in smem; incremental colsum repair (<=45 entries) from src with
// window coverage. Outputs window (r,c) + maxima; inits g_eq.
// ---------------------------------------------------------------------------
__global__ __launch_bounds__(512)
void greedy6_kernel(const float* __restrict__ in) {
    const int b = blockIdx.x, tid = threadIdx.x;
    const int warp = tid >> 5, lane = tid & 31;
    const float* src = in + (size_t)b * H * H;
    float* cs = g_colsum + (size_t)b * AW * H;

    __shared__ float s_pv[NPART];
    __shared__ int   s_pi[NPART];
    __shared__ float s_rv[16];
    __shared__ int   s_ri[16];
    __shared__ float s_win[25];
    __shared__ int   s_wr[KCL], s_wc[KCL];
    __shared__ float s_mv[KCL];
    __shared__ int   s_r, s_c;

    for (int i = tid; i < NPART; i += 512) {
        s_pv[i] = g_pv[b * NPART + i];
        s_pi[i] = g_pi[b * NPART + i];
    }
    if (tid < KCL) g_eq[b * KCL + tid] = 0x7fffffff;
    __syncthreads();

    for (int it = 0; it < KCL; it++) {
        // A: argmax over 1936 smem partials (two-level shuffle tree)
        {
            float bv = -1.0f; int bi = 0x7fffffff;
            for (int i = tid; i < NPART; i += 512) better(s_pv[i], s_pi[i], bv, bi);
            #pragma unroll
            for (int off = 16; off; off >>= 1) {
                float ov = __shfl_down_sync(0xffffffffu, bv, off);
                int   oi = __shfl_down_sync(0xffffffffu, bi, off);
                better(ov, oi, bv, bi);
            }
            if (lane == 0) { s_rv[warp] = bv; s_ri[warp] = bi; }
        }
        __syncthreads();
        if (warp == 0) {
            float bv = (lane < 16) ? s_rv[lane] : -1.0f;
            int   bi = (lane < 16) ? s_ri[lane] : 0x7fffffff;
            #pragma unroll
            for (int off = 8; off; off >>= 1) {
                float ov = __shfl_down_sync(0xffffffffu, bv, off);
                int   oi = __shfl_down_sync(0xffffffffu, bi, off);
                better(ov, oi, bv, bi);
            }
            if (lane == 0) { s_r = bi / AW; s_c = bi % AW; }
        }
        __syncthreads();
        const int r = s_r, c = s_c;

        // B: window max (value = orig unless covered by window j < it)
        if (tid < 25) {
            int y = r + tid / 5, x = c + tid % 5;
            float v = src[y * H + x];
            for (int j = 0; j < it; j++)
                if ((unsigned)(y - s_wr[j]) < 5u && (unsigned)(x - s_wc[j]) < 5u) v = 0.0f;
            s_win[tid] = v;
        }
        __syncthreads();
        if (tid == 0) {
            float mv = -1.0f;
            #pragma unroll
            for (int i = 0; i < 25; i++) mv = fmaxf(mv, s_win[i]);
            s_mv[it] = mv; s_wr[it] = r; s_wc[it] = c;
        }

        // C: incremental colsum repair (<=45 entries), coverage j <= it
        const int r0c = max(0, r - 4), r1c = min(AW - 1, r + 4);
        {
            int nc = (r1c - r0c + 1) * 5;
            if (tid < nc) {
                int rr = r0c + tid / 5, cc = c + tid % 5;
                float s = 0.0f;
                #pragma unroll
                for (int d = 0; d < 5; d++) {
                    int y = rr + d;
                    float v = src[y * H + cc];
                    if ((unsigned)(y - r) < 5u && (unsigned)(cc - c) < 5u) v = 0.0f;
                    for (int j = 0; j < it; j++)
                        if ((unsigned)(y - s_wr[j]) < 5u && (unsigned)(cc - s_wc[j]) < 5u) v = 0.0f;
                    s = s + v;   // left-assoc, matches scan0 ring
                }
                cs[rr * H + cc] = s;
            }
        }
        __syncthreads();

        // D: recompute affected partials (<= 9 rows x <= 2 segs)
        {
            const int jlo = max(0, c - 4), jhi = min(AW - 1, c + 4);
            const int s0 = jlo / SEG, s1 = jhi / SEG;
            const int nsegs = s1 - s0 + 1;
            const int npairs = (r1c - r0c + 1) * nsegs;
            for (int p = warp; p < npairs; p += 16) {
                int rr = r0c + p / nsegs, sg = s0 + p % nsegs;
                const float* row = cs + rr * H;
                float bv2 = -1.0f; int bi2 = 0x7fffffff;
                for (int j = sg * SEG + lane; j < sg * SEG + SEG; j += 32) {
                    float v = row[j] + row[j + 1] + row[j + 2] + row[j + 3] + row[j + 4];
                    better(v, rr * AW + j, bv2, bi2);
                }
                #pragma unroll
                for (int off = 16; off; off >>= 1) {
                    float ov = __shfl_down_sync(0xffffffffu, bv2, off);
                    int   oi = __shfl_down_sync(0xffffffffu, bi2, off);
                    better(ov, oi, bv2, bi2);
                }
                if (lane == 0) { s_pv[rr * NSEG + sg] = bv2; s_pi[rr * NSEG + sg] = bi2; }
            }
        }
        __syncthreads();
    }

    if (tid < KCL) {
        g_wr[b * KCL + tid] = s_wr[tid];
        g_wc[b * KCL + tid] = s_wc[tid];
        g_mv[b * KCL + tid] = s_mv[tid];
    }
}

// ---------------------------------------------------------------------------
// eq: first-occurrence scan, grid (NB, 8) x 256 — full chip. Branchless
// exact-bit filter (positive finite floats: float eq <=> bit eq), 4-way
// unrolled loads for MLP. Coverage by earlier windows -> 0 (never equal).
// Global atomicMin (commutative -> deterministic).
// ---------------------------------------------------------------------------
__global__ __launch_bounds__(256)
void eq_kernel(const float* __restrict__ in) {
    const int b = blockIdx.x, cb = blockIdx.y, tid = threadIdx.x;

    __shared__ unsigned s_p[KCL];
    __shared__ int      s_wr[KCL], s_wc[KCL];

    if (tid < KCL) {
        s_p[tid]  = __float_as_uint(g_mv[b * KCL + tid]);
        s_wr[tid] = g_wr[b * KCL + tid];
        s_wc[tid] = g_wc[b * KCL + tid];
    }
    __syncthreads();
    const unsigned p0 = s_p[0], p1 = s_p[1], p2 = s_p[2],
                   p3 = s_p[3], p4 = s_p[4], p5 = s_p[5];

    const uint4* h4 = (const uint4*)(in + (size_t)b * H * H);
    const int b0 = cb * CE4, e0 = min(NE4, b0 + CE4);

    for (int tt = b0 + tid; tt < e0; tt += 256 * 4) {
        uint4 v[4];
        bool ok[4];
        #pragma unroll
        for (int q = 0; q < 4; q++) {
            int idx = tt + q * 256;
            ok[q] = idx < e0;
            v[q] = ok[q] ? h4[idx] : make_uint4(0u, 0u, 0u, 0u);
        }
        bool hit = false;
        #pragma unroll
        for (int q = 0; q < 4; q++) {
            hit = hit |
                (v[q].x == p0) | (v[q].y == p0) | (v[q].z == p0) | (v[q].w == p0) |
                (v[q].x == p1) | (v[q].y == p1) | (v[q].z == p1) | (v[q].w == p1) |
                (v[q].x == p2) | (v[q].y == p2) | (v[q].z == p2) | (v[q].w == p2) |
                (v[q].x == p3) | (v[q].y == p3) | (v[q].z == p3) | (v[q].w == p3) |
                (v[q].x == p4) | (v[q].y == p4) | (v[q].z == p4) | (v[q].w == p4) |
                (v[q].x == p5) | (v[q].y == p5) | (v[q].z == p5) | (v[q].w == p5);
        }
        if (!hit) continue;   // taken almost never (exact-bit matches only)
        #pragma unroll
        for (int q = 0; q < 4; q++) {
            if (!ok[q]) continue;
            #pragma unroll
            for (int u = 0; u < 4; u++) {
                unsigned val = (u == 0) ? v[q].x : (u == 1) ? v[q].y
                             : (u == 2) ? v[q].z : v[q].w;
                int id = (tt + q * 256) * 4 + u;
                #pragma unroll
                for (int i = 0; i < KCL; i++) {
                    unsigned pp = (i == 0) ? p0 : (i == 1) ? p1 : (i == 2) ? p2
                                : (i == 3) ? p3 : (i == 4) ? p4 : p5;
                    if (val == pp) {
                        int y = id / H, x = id - y * H;
                        bool cov = false;
                        for (int j = 0; j < i; j++)
                            if ((unsigned)(y - s_wr[j]) < 5u && (unsigned)(x - s_wc[j]) < 5u) cov = true;
                        if (!cov) atomicMin(&g_eq[b * KCL + i], id);
                    }
                }
            }
        }
    }
}

// ---------------------------------------------------------------------------
// refine: 10 mean-shift iterations (R6-proven form: 5 warps/cluster; centers
// persist in registers, all threads redundantly recompute them — identical
// fp op order -> deterministic), then round + clamped 4x4 confidences.
// ---------------------------------------------------------------------------
__global__ __launch_bounds__(1024)
void refine_kernel(const float* __restrict__ in, float* __restrict__ out) {
    const int b = blockIdx.x, tid = threadIdx.x;
    const int warp = tid >> 5, lane = tid & 31;
    const float* src = in + (size_t)b * H * H;

    __shared__ float pY[KCL][RW], pX[KCL][RW], pW[KCL][RW];
    __shared__ int   s_eq[KCL];

    if (tid < KCL) s_eq[tid] = g_eq[b * KCL + tid];
    __syncthreads();

    float rcy[KCL], rcx[KCL];
    #pragma unroll
    for (int i = 0; i < KCL; i++) {
        int fh = s_eq[i];
        rcy[i] = (float)(fh / H);
        rcx[i] = (float)(fh % H);
    }

    const int k = warp / RW;            // 0..5 for warps 0..29; warps 30,31 idle
    const int sw = warp - k * RW;
    const bool active = (warp < KCL * RW);

    for (int it = 0; it < ITERS; it++) {
        if (active) {
            float cy = rcy[0], cx = rcx[0];
            if (k == 1) { cy = rcy[1]; cx = rcx[1]; }
            if (k == 2) { cy = rcy[2]; cx = rcx[2]; }
            if (k == 3) { cy = rcy[3]; cx = rcx[3]; }
            if (k == 4) { cy = rcy[4]; cx = rcx[4]; }
            if (k == 5) { cy = rcy[5]; cx = rcx[5]; }

            const int y0 = max(0, (int)floorf(cy - 12.0f));
            const int y1 = min(H - 1, (int)ceilf(cy + 12.0f));
            const int x0 = max(0, (int)floorf(cx - 12.0f));
            const int x1 = min(H - 1, (int)ceilf(cx + 12.0f));
            const int w  = x1 - x0 + 1;        // <= 26 <= 32 lanes

            float sy = 0.0f, sx = 0.0f, swt = 0.0f;
            const int x = x0 + lane;
            if (lane < w) {
                const float fx = (float)x;
                const float dx = fx - cx;
                for (int y = y0 + sw; y <= y1; y += RW) {
                    float fy = (float)y;
                    float dy = fy - cy;
                    float d2 = fmaxf(dy * dy + dx * dx, 1e-6f);
                    if (d2 < 144.0f) {
                        float m2 = d2;
                        #pragma unroll
                        for (int k2 = 0; k2 < KCL; k2++) {
                            float ey = fy - rcy[k2], ex = fx - rcx[k2];
                            m2 = fminf(m2, fmaxf(ey * ey + ex * ex, 1e-6f));
                        }
                        float wgt = src[y * H + x] * sqrtf(m2) / d2;
                        sy += wgt * fy;
                        sx += wgt * fx;
                        swt += wgt;
                    }
                }
            }
            #pragma unroll
            for (int off = 16; off; off >>= 1) {
                sy  += __shfl_down_sync(0xffffffffu, sy, off);
                sx  += __shfl_down_sync(0xffffffffu, sx, off);
                swt += __shfl_down_sync(0xffffffffu, swt, off);
            }
            if (lane == 0) { pY[k][sw] = sy; pX[k][sw] = sx; pW[k][sw] = swt; }
        }
        __syncthreads();
        // every thread recomputes all centers identically (constant indices)
        #pragma unroll
        for (int k2 = 0; k2 < KCL; k2++) {
            float ay = pY[k2][0] + pY[k2][1] + pY[k2][2] + pY[k2][3] + pY[k2][4];
            float ax = pX[k2][0] + pX[k2][1] + pX[k2][2] + pX[k2][3] + pX[k2][4];
            float aw = pW[k2][0] + pW[k2][1] + pW[k2][2] + pW[k2][3] + pW[k2][4];
            rcy[k2] = ay / aw;
            rcx[k2] = ax / aw;
        }
        __syncthreads();   // protect pY/pX/pW reuse next iteration
    }

    if (tid < KCL) {
        float fy = rcy[0], fx = rcx[0];
        if (tid == 1) { fy = rcy[1]; fx = rcx[1]; }
        if (tid == 2) { fy = rcy[2]; fx = rcx[2]; }
        if (tid == 3) { fy = rcy[3]; fx = rcx[3]; }
        if (tid == 4) { fy = rcy[4]; fx = rcx[4]; }
        if (tid == 5) { fy = rcy[5]; fx = rcx[5]; }
        int iy = (int)rintf(fy);   // round-half-to-even == jnp.round
        int ix = (int)rintf(fx);
        out[(b * KCL + tid) * 2 + 0] = (float)iy;
        out[(b * KCL + tid) * 2 + 1] = (float)ix;
        int sy0 = min(max(iy - 2, 0), H - 4);   // dynamic_slice clamp
        int sx0 = min(max(ix - 2, 0), H - 4);
        float cf = 0.0f;
        #pragma unroll
        for (int di = 0; di < 4; di++)
            #pragma unroll
            for (int dj = 0; dj < 4; dj++)
                cf += src[(sy0 + di) * H + (sx0 + dj)];
        out[NB * KCL * 2 + b * KCL + tid] = cf;
    }
}

extern "C" void kernel_launch(void* const* d_in, const int* in_sizes, int n_in,
                              void* d_out, int out_size) {
    const float* hm = (const float*)d_in[0];
    float* out = (float*)d_out;

    scan0_kernel<<<dim3(NB, NCH0), 128>>>(hm);
    greedy6_kernel<<<NB, 512>>>(hm);
    eq_kernel<<<dim3(NB, NCHE), 256>>>(hm);
    refine_kernel<<<NB, 1024>>>(hm, out);
}

// round 9
// speedup vs baseline: 1.3732x; 1.0695x over previous
#include <cuda_runtime.h>
#include <cuda_bf16.h>

#define H      488
#define AW     484          // H - 5 + 1
#define KCL    6
#define NB     32
#define ITERS  10
#define SEG    121          // 484 = 4 * 121 windows per row
#define NSEG   4
#define NPART  (AW * NSEG)  // 1936 partials per batch
#define CR0    8            // rows per scan0 chunk
#define NCH0   61           // ceil(484/8)
#define NE4    (H * H / 4)  // 59536 uint4/float4 per batch
#define NCHE   8            // eq chunks per batch
#define CE4    7442         // NE4 / 8
#define RW     5            // warps per cluster in refine (30 of 32 warps)

// Scratch (allocation-free: __device__ globals)
__device__ float g_colsum[NB * AW * H];     // vertical 5-sums
__device__ float g_pv[NB * NPART];          // per-(row,seg) argmax value
__device__ int   g_pi[NB * NPART];          // per-(row,seg) argmax flat window idx
__device__ int   g_wr[NB * KCL], g_wc[NB * KCL];
__device__ float g_mv[NB * KCL];
__device__ int   g_eq[NB * KCL];            // first-occurrence flat index

__device__ __forceinline__ void better(float v, int i, float& bv, int& bi) {
    if (v > bv || (v == bv && i < bi)) { bv = v; bi = i; }
}

// ---------------------------------------------------------------------------
// scan0: input -> colsum (global, float4) + initial argmax partials.
// grid (NB, 61) x 128. 8 rows per chunk, 4 cols per thread (vectorized).
// ---------------------------------------------------------------------------
__global__ __launch_bounds__(128)
void scan0_kernel(const float* __restrict__ in) {
    const int b = blockIdx.x, cb = blockIdx.y, tid = threadIdx.x;
    const float* src = in + (size_t)b * H * H;
    float* cs = g_colsum + (size_t)b * AW * H;

    __shared__ float s_cs[CR0][H];

    const int R0 = CR0 * cb, R1 = min(AW, R0 + CR0);

    // column 5-sums, 4 columns per thread via float4 (left-assoc per column)
    if (tid < H / 4) {
        const float4* s4 = (const float4*)src;
        float4* c4 = (float4*)cs;
        const int HQ = H / 4;                 // 122 float4 per row
        float4 w0 = s4[(R0 + 0) * HQ + tid], w1 = s4[(R0 + 1) * HQ + tid],
               w2 = s4[(R0 + 2) * HQ + tid], w3 = s4[(R0 + 3) * HQ + tid], w4;
        for (int i = R0; i < R1; i++) {
            w4 = s4[(i + 4) * HQ + tid];
            float4 s;
            s.x = w0.x + w1.x + w2.x + w3.x + w4.x;
            s.y = w0.y + w1.y + w2.y + w3.y + w4.y;
            s.z = w0.z + w1.z + w2.z + w3.z + w4.z;
            s.w = w0.w + w1.w + w2.w + w3.w + w4.w;
            *(float4*)&s_cs[i - R0][tid * 4] = s;
            c4[i * HQ + tid] = s;
            w0 = w1; w1 = w2; w2 = w3; w3 = w4;
        }
    }
    __syncthreads();

    // partials: up to 32 (row,seg) pairs, 4 sub-threads each
    const int pair = tid >> 2, sub = tid & 3;
    const int lr = pair >> 2, sg = pair & 3;
    const int nrows = R1 - R0;

    float bv = -1.0f; int bi = 0x7fffffff;
    if (lr < nrows) {
        const float* row = s_cs[lr];
        const int jbeg = sg * SEG;
        for (int j = jbeg + sub; j < jbeg + SEG; j += 4) {
            float v = row[j] + row[j + 1] + row[j + 2] + row[j + 3] + row[j + 4];
            better(v, (R0 + lr) * AW + j, bv, bi);
        }
    }
    #pragma unroll
    for (int off = 2; off; off >>= 1) {
        float ov = __shfl_down_sync(0xffffffffu, bv, off);
        int   oi = __shfl_down_sync(0xffffffffu, bi, off);
        better(ov, oi, bv, bi);
    }
    if (sub == 0 && lr < nrows) {
        g_pv[b * NPART + (R0 + lr) * NSEG + sg] = bv;
        g_pi[b * NPART + (R0 + lr) * NSEG + sg] = bi;
    }
}

// ---------------------------------------------------------------------------
// greedy6: 6 greedy extractions per batch. grid NB x 512.
// 4 barriers/iter: A(2) -> {B on warp 0 || C on warps 1+} (1) -> D (1).
// ---------------------------------------------------------------------------
__global__ __launch_bounds__(512)
void greedy6_kernel(const float* __restrict__ in) {
    const int b = blockIdx.x, tid = threadIdx.x;
    const int warp = tid >> 5, lane = tid & 31;
    const float* src = in + (size_t)b * H * H;
    float* cs = g_colsum + (size_t)b * AW * H;

    __shared__ float s_pv[NPART];
    __shared__ int   s_pi[NPART];
    __shared__ float s_rv[16];
    __shared__ int   s_ri[16];
    __shared__ int   s_wr[KCL], s_wc[KCL];
    __shared__ float s_mv[KCL];
    __shared__ int   s_r, s_c;

    for (int i = tid; i < NPART; i += 512) {
        s_pv[i] = g_pv[b * NPART + i];
        s_pi[i] = g_pi[b * NPART + i];
    }
    if (tid < KCL) g_eq[b * KCL + tid] = 0x7fffffff;
    __syncthreads();

    for (int it = 0; it < KCL; it++) {
        // A: argmax over 1936 smem partials (two-level shuffle tree)
        {
            float bv = -1.0f; int bi = 0x7fffffff;
            for (int i = tid; i < NPART; i += 512) better(s_pv[i], s_pi[i], bv, bi);
            #pragma unroll
            for (int off = 16; off; off >>= 1) {
                float ov = __shfl_down_sync(0xffffffffu, bv, off);
                int   oi = __shfl_down_sync(0xffffffffu, bi, off);
                better(ov, oi, bv, bi);
            }
            if (lane == 0) { s_rv[warp] = bv; s_ri[warp] = bi; }
        }
        __syncthreads();
        if (warp == 0) {
            float bv = (lane < 16) ? s_rv[lane] : -1.0f;
            int   bi = (lane < 16) ? s_ri[lane] : 0x7fffffff;
            #pragma unroll
            for (int off = 8; off; off >>= 1) {
                float ov = __shfl_down_sync(0xffffffffu, bv, off);
                int   oi = __shfl_down_sync(0xffffffffu, bi, off);
                better(ov, oi, bv, bi);
            }
            if (lane == 0) { s_r = bi / AW; s_c = bi % AW; }
        }
        __syncthreads();
        const int r = s_r, c = s_c;
        const int r0c = max(0, r - 4), r1c = min(AW - 1, r + 4);

        if (warp == 0) {
            // B: window max on warp 0 (value = orig unless covered earlier)
            float v = -1.0f;
            if (lane < 25) {
                int y = r + lane / 5, x = c + lane % 5;
                v = src[y * H + x];
                for (int j = 0; j < it; j++)
                    if ((unsigned)(y - s_wr[j]) < 5u && (unsigned)(x - s_wc[j]) < 5u) v = 0.0f;
            }
            #pragma unroll
            for (int off = 16; off; off >>= 1)
                v = fmaxf(v, __shfl_down_sync(0xffffffffu, v, off));
            if (lane == 0) { s_mv[it] = v; s_wr[it] = r; s_wc[it] = c; }
        } else {
            // C (warps 1+): incremental colsum repair (<=45 entries)
            int nc = (r1c - r0c + 1) * 5;
            int idx = tid - 32;
            if (idx < nc) {
                int rr = r0c + idx / 5, cc = c + idx % 5;
                float s = 0.0f;
                #pragma unroll
                for (int d = 0; d < 5; d++) {
                    int y = rr + d;
                    float v = src[y * H + cc];
                    if ((unsigned)(y - r) < 5u && (unsigned)(cc - c) < 5u) v = 0.0f;
                    for (int j = 0; j < it; j++)
                        if ((unsigned)(y - s_wr[j]) < 5u && (unsigned)(cc - s_wc[j]) < 5u) v = 0.0f;
                    s = s + v;   // left-assoc, matches scan0 ring
                }
                cs[rr * H + cc] = s;
            }
        }
        __syncthreads();

        // D: recompute affected partials (<= 9 rows x <= 2 segs)
        {
            const int jlo = max(0, c - 4), jhi = min(AW - 1, c + 4);
            const int s0 = jlo / SEG, s1 = jhi / SEG;
            const int nsegs = s1 - s0 + 1;
            const int npairs = (r1c - r0c + 1) * nsegs;
            for (int p = warp; p < npairs; p += 16) {
                int rr = r0c + p / nsegs, sg = s0 + p % nsegs;
                const float* row = cs + rr * H;
                float bv2 = -1.0f; int bi2 = 0x7fffffff;
                for (int j = sg * SEG + lane; j < sg * SEG + SEG; j += 32) {
                    float v = row[j] + row[j + 1] + row[j + 2] + row[j + 3] + row[j + 4];
                    better(v, rr * AW + j, bv2, bi2);
                }
                #pragma unroll
                for (int off = 16; off; off >>= 1) {
                    float ov = __shfl_down_sync(0xffffffffu, bv2, off);
                    int   oi = __shfl_down_sync(0xffffffffu, bi2, off);
                    better(ov, oi, bv2, bi2);
                }
                if (lane == 0) { s_pv[rr * NSEG + sg] = bv2; s_pi[rr * NSEG + sg] = bi2; }
            }
        }
        __syncthreads();
    }

    if (tid < KCL) {
        g_wr[b * KCL + tid] = s_wr[tid];
        g_wc[b * KCL + tid] = s_wc[tid];
        g_mv[b * KCL + tid] = s_mv[tid];
    }
}

// ---------------------------------------------------------------------------
// eq: first-occurrence scan, grid (NB, 8) x 256 — full chip. Branchless
// exact-bit filter, 4-way unrolled loads for MLP. Global atomicMin.
// ---------------------------------------------------------------------------
__global__ __launch_bounds__(256)
void eq_kernel(const float* __restrict__ in) {
    const int b = blockIdx.x, cb = blockIdx.y, tid = threadIdx.x;

    __shared__ unsigned s_p[KCL];
    __shared__ int      s_wr[KCL], s_wc[KCL];

    if (tid < KCL) {
        s_p[tid]  = __float_as_uint(g_mv[b * KCL + tid]);
        s_wr[tid] = g_wr[b * KCL + tid];
        s_wc[tid] = g_wc[b * KCL + tid];
    }
    __syncthreads();
    const unsigned p0 = s_p[0], p1 = s_p[1], p2 = s_p[2],
                   p3 = s_p[3], p4 = s_p[4], p5 = s_p[5];

    const uint4* h4 = (const uint4*)(in + (size_t)b * H * H);
    const int b0 = cb * CE4, e0 = min(NE4, b0 + CE4);

    for (int tt = b0 + tid; tt < e0; tt += 256 * 4) {
        uint4 v[4];
        bool ok[4];
        #pragma unroll
        for (int q = 0; q < 4; q++) {
            int idx = tt + q * 256;
            ok[q] = idx < e0;
            v[q] = ok[q] ? h4[idx] : make_uint4(0u, 0u, 0u, 0u);
        }
        bool hit = false;
        #pragma unroll
        for (int q = 0; q < 4; q++) {
            hit = hit |
                (v[q].x == p0) | (v[q].y == p0) | (v[q].z == p0) | (v[q].w == p0) |
                (v[q].x == p1) | (v[q].y == p1) | (v[q].z == p1) | (v[q].w == p1) |
                (v[q].x == p2) | (v[q].y == p2) | (v[q].z == p2) | (v[q].w == p2) |
                (v[q].x == p3) | (v[q].y == p3) | (v[q].z == p3) | (v[q].w == p3) |
                (v[q].x == p4) | (v[q].y == p4) | (v[q].z == p4) | (v[q].w == p4) |
                (v[q].x == p5) | (v[q].y == p5) | (v[q].z == p5) | (v[q].w == p5);
        }
        if (!hit) continue;   // taken almost never (exact-bit matches only)
        #pragma unroll
        for (int q = 0; q < 4; q++) {
            if (!ok[q]) continue;
            #pragma unroll
            for (int u = 0; u < 4; u++) {
                unsigned val = (u == 0) ? v[q].x : (u == 1) ? v[q].y
                             : (u == 2) ? v[q].z : v[q].w;
                int id = (tt + q * 256) * 4 + u;
                #pragma unroll
                for (int i = 0; i < KCL; i++) {
                    unsigned pp = (i == 0) ? p0 : (i == 1) ? p1 : (i == 2) ? p2
                                : (i == 3) ? p3 : (i == 4) ? p4 : p5;
                    if (val == pp) {
                        int y = id / H, x = id - y * H;
                        bool cov = false;
                        for (int j = 0; j < i; j++)
                            if ((unsigned)(y - s_wr[j]) < 5u && (unsigned)(x - s_wc[j]) < 5u) cov = true;
                        if (!cov) atomicMin(&g_eq[b * KCL + i], id);
                    }
                }
            }
        }
    }
}

// ---------------------------------------------------------------------------
// refine: 10 mean-shift iterations, 5 warps/cluster. Fast-math weight
// (rsqrtf + __fdividef — deterministic HW approx, error ~1e-6 << 1e-3 tol),
// x-invariants hoisted out of the y loop, ONE barrier/iter via
// double-buffered partials. Then round + clamped 4x4 confidences.
// ---------------------------------------------------------------------------
__global__ __launch_bounds__(1024)
void refine_kernel(const float* __restrict__ in, float* __restrict__ out) {
    const int b = blockIdx.x, tid = threadIdx.x;
    const int warp = tid >> 5, lane = tid & 31;
    const float* src = in + (size_t)b * H * H;

    __shared__ float pY[2][KCL][RW], pX[2][KCL][RW], pW[2][KCL][RW];
    __shared__ int   s_eq[KCL];

    if (tid < KCL) s_eq[tid] = g_eq[b * KCL + tid];
    __syncthreads();

    float rcy[KCL], rcx[KCL];
    #pragma unroll
    for (int i = 0; i < KCL; i++) {
        int fh = s_eq[i];
        rcy[i] = (float)(fh / H);
        rcx[i] = (float)(fh % H);
    }

    const int k = warp / RW;            // 0..5 for warps 0..29; warps 30,31 idle
    const int sw = warp - k * RW;
    const bool active = (warp < KCL * RW);

    for (int it = 0; it < ITERS; it++) {
        const int buf = it & 1;
        if (active) {
            float cy = rcy[0], cx = rcx[0];
            if (k == 1) { cy = rcy[1]; cx = rcx[1]; }
            if (k == 2) { cy = rcy[2]; cx = rcx[2]; }
            if (k == 3) { cy = rcy[3]; cx = rcx[3]; }
            if (k == 4) { cy = rcy[4]; cx = rcx[4]; }
            if (k == 5) { cy = rcy[5]; cx = rcx[5]; }

            const int y0 = max(0, (int)floorf(cy - 12.0f));
            const int y1 = min(H - 1, (int)ceilf(cy + 12.0f));
            const int x0 = max(0, (int)floorf(cx - 12.0f));
            const int x1 = min(H - 1, (int)ceilf(cx + 12.0f));
            const int w  = x1 - x0 + 1;        // <= 26 <= 32 lanes

            float sy = 0.0f, sx = 0.0f, swt = 0.0f;
            const int x = x0 + lane;
            if (lane < w) {
                const float fx = (float)x;
                const float dx2 = (fx - cx) * (fx - cx);
                // x-invariants for the min-distance loop
                float ex2[KCL];
                #pragma unroll
                for (int i = 0; i < KCL; i++) {
                    float ex = fx - rcx[i];
                    ex2[i] = ex * ex;
                }
                for (int y = y0 + sw; y <= y1; y += RW) {
                    const float fy = (float)y;
                    const float dy = fy - cy;
                    const float d2 = fmaxf(fmaf(dy, dy, dx2), 1e-6f);
                    if (d2 < 144.0f) {
                        float m2 = d2;
                        #pragma unroll
                        for (int k2 = 0; k2 < KCL; k2++) {
                            float ey = fy - rcy[k2];
                            m2 = fminf(m2, fmaxf(fmaf(ey, ey, ex2[k2]), 1e-6f));
                        }
                        // sqrt(m2)/d2 via HW approximations (deterministic)
                        float s = m2 * rsqrtf(m2);               // ~sqrt(m2)
                        float wgt = __fdividef(src[y * H + x] * s, d2);
                        sy = fmaf(wgt, fy, sy);
                        sx = fmaf(wgt, fx, sx);
                        swt += wgt;
                    }
                }
            }
            #pragma unroll
            for (int off = 16; off; off >>= 1) {
                sy  += __shfl_down_sync(0xffffffffu, sy, off);
                sx  += __shfl_down_sync(0xffffffffu, sx, off);
                swt += __shfl_down_sync(0xffffffffu, swt, off);
            }
            if (lane == 0) { pY[buf][k][sw] = sy; pX[buf][k][sw] = sx; pW[buf][k][sw] = swt; }
        }
        __syncthreads();
        // every thread recomputes all centers identically (constant indices);
        // double buffering makes the second barrier unnecessary.
        #pragma unroll
        for (int k2 = 0; k2 < KCL; k2++) {
            float ay = pY[buf][k2][0] + pY[buf][k2][1] + pY[buf][k2][2] + pY[buf][k2][3] + pY[buf][k2][4];
            float ax = pX[buf][k2][0] + pX[buf][k2][1] + pX[buf][k2][2] + pX[buf][k2][3] + pX[buf][k2][4];
            float aw = pW[buf][k2][0] + pW[buf][k2][1] + pW[buf][k2][2] + pW[buf][k2][3] + pW[buf][k2][4];
            rcy[k2] = __fdividef(ay, aw);
            rcx[k2] = __fdividef(ax, aw);
        }
    }

    if (tid < KCL) {
        float fy = rcy[0], fx = rcx[0];
        if (tid == 1) { fy = rcy[1]; fx = rcx[1]; }
        if (tid == 2) { fy = rcy[2]; fx = rcx[2]; }
        if (tid == 3) { fy = rcy[3]; fx = rcx[3]; }
        if (tid == 4) { fy = rcy[4]; fx = rcx[4]; }
        if (tid == 5) { fy = rcy[5]; fx = rcx[5]; }
        int iy = (int)rintf(fy);   // round-half-to-even == jnp.round
        int ix = (int)rintf(fx);
        out[(b * KCL + tid) * 2 + 0] = (float)iy;
        out[(b * KCL + tid) * 2 + 1] = (float)ix;
        int sy0 = min(max(iy - 2, 0), H - 4);   // dynamic_slice clamp
        int sx0 = min(max(ix - 2, 0), H - 4);
        float cf = 0.0f;
        #pragma unroll
        for (int di = 0; di < 4; di++)
            #pragma unroll
            for (int dj = 0; dj < 4; dj++)
                cf += src[(sy0 + di) * H + (sx0 + dj)];
        out[NB * KCL * 2 + b * KCL + tid] = cf;
    }
}

extern "C" void kernel_launch(void* const* d_in, const int* in_sizes, int n_in,
                              void* d_out, int out_size) {
    const float* hm = (const float*)d_in[0];
    float* out = (float*)d_out;

    scan0_kernel<<<dim3(NB, NCH0), 128>>>(hm);
    greedy6_kernel<<<NB, 512>>>(hm);
    eq_kernel<<<dim3(NB, NCHE), 256>>>(hm);
    refine_kernel<<<NB, 1024>>>(hm, out);
}

// round 10
// speedup vs baseline: 1.5307x; 1.1147x over previous
#include <cuda_runtime.h>
#include <cuda_bf16.h>

#define H      488
#define AW     484          // H - 5 + 1
#define KCL    6
#define NB     32
#define ITERS  10
#define SEG    121          // 484 = 4 * 121 windows per row
#define NSEG   4
#define NPART  (AW * NSEG)  // 1936 partials per batch
#define CR0    8            // rows per scan0 chunk
#define NCH0   61           // ceil(484/8)
#define NE4    (H * H / 4)  // 59536 uint4/float4 per batch
#define NCHE   8            // eq chunks per batch
#define CE4    7442         // NE4 / 8
#define RW     5            // warps per cluster in refine (30 of 32 warps)

// Scratch (allocation-free: __device__ globals)
__device__ float g_colsum[NB * AW * H];     // vertical 5-sums
__device__ float g_pv[NB * NPART];          // per-(row,seg) argmax value
__device__ int   g_pi[NB * NPART];          // per-(row,seg) argmax flat window idx
__device__ int   g_wr[NB * KCL], g_wc[NB * KCL];
__device__ float g_mv[NB * KCL];
__device__ int   g_eq[NB * KCL];            // first-occurrence flat index

__device__ __forceinline__ void better(float v, int i, float& bv, int& bi) {
    if (v > bv || (v == bv && i < bi)) { bv = v; bi = i; }
}

// ---------------------------------------------------------------------------
// scan0: input -> colsum (global, float4) + initial argmax partials.
// grid (NB, 61) x 128. 8 rows per chunk, 4 cols per thread (vectorized).
// ---------------------------------------------------------------------------
__global__ __launch_bounds__(128)
void scan0_kernel(const float* __restrict__ in) {
    const int b = blockIdx.x, cb = blockIdx.y, tid = threadIdx.x;
    const float* src = in + (size_t)b * H * H;
    float* cs = g_colsum + (size_t)b * AW * H;

    __shared__ float s_cs[CR0][H];

    const int R0 = CR0 * cb, R1 = min(AW, R0 + CR0);

    // column 5-sums, 4 columns per thread via float4 (left-assoc per column)
    if (tid < H / 4) {
        const float4* s4 = (const float4*)src;
        float4* c4 = (float4*)cs;
        const int HQ = H / 4;                 // 122 float4 per row
        float4 w0 = s4[(R0 + 0) * HQ + tid], w1 = s4[(R0 + 1) * HQ + tid],
               w2 = s4[(R0 + 2) * HQ + tid], w3 = s4[(R0 + 3) * HQ + tid], w4;
        for (int i = R0; i < R1; i++) {
            w4 = s4[(i + 4) * HQ + tid];
            float4 s;
            s.x = w0.x + w1.x + w2.x + w3.x + w4.x;
            s.y = w0.y + w1.y + w2.y + w3.y + w4.y;
            s.z = w0.z + w1.z + w2.z + w3.z + w4.z;
            s.w = w0.w + w1.w + w2.w + w3.w + w4.w;
            *(float4*)&s_cs[i - R0][tid * 4] = s;
            c4[i * HQ + tid] = s;
            w0 = w1; w1 = w2; w2 = w3; w3 = w4;
        }
    }
    __syncthreads();

    // partials: up to 32 (row,seg) pairs, 4 sub-threads each
    const int pair = tid >> 2, sub = tid & 3;
    const int lr = pair >> 2, sg = pair & 3;
    const int nrows = R1 - R0;

    float bv = -1.0f; int bi = 0x7fffffff;
    if (lr < nrows) {
        const float* row = s_cs[lr];
        const int jbeg = sg * SEG;
        for (int j = jbeg + sub; j < jbeg + SEG; j += 4) {
            float v = row[j] + row[j + 1] + row[j + 2] + row[j + 3] + row[j + 4];
            better(v, (R0 + lr) * AW + j, bv, bi);
        }
    }
    #pragma unroll
    for (int off = 2; off; off >>= 1) {
        float ov = __shfl_down_sync(0xffffffffu, bv, off);
        int   oi = __shfl_down_sync(0xffffffffu, bi, off);
        better(ov, oi, bv, bi);
    }
    if (sub == 0 && lr < nrows) {
        g_pv[b * NPART + (R0 + lr) * NSEG + sg] = bv;
        g_pi[b * NPART + (R0 + lr) * NSEG + sg] = bi;
    }
}

// ---------------------------------------------------------------------------
// greedy6: 6 greedy extractions per batch. grid NB x 512.
// 4 barriers/iter: A(2) -> {B on warp 0 || C on warps 1+} (1) -> D (1).
// ---------------------------------------------------------------------------
__global__ __launch_bounds__(512)
void greedy6_kernel(const float* __restrict__ in) {
    const int b = blockIdx.x, tid = threadIdx.x;
    const int warp = tid >> 5, lane = tid & 31;
    const float* src = in + (size_t)b * H * H;
    float* cs = g_colsum + (size_t)b * AW * H;

    __shared__ float s_pv[NPART];
    __shared__ int   s_pi[NPART];
    __shared__ float s_rv[16];
    __shared__ int   s_ri[16];
    __shared__ int   s_wr[KCL], s_wc[KCL];
    __shared__ float s_mv[KCL];
    __shared__ int   s_r, s_c;

    for (int i = tid; i < NPART; i += 512) {
        s_pv[i] = g_pv[b * NPART + i];
        s_pi[i] = g_pi[b * NPART + i];
    }
    if (tid < KCL) g_eq[b * KCL + tid] = 0x7fffffff;
    __syncthreads();

    for (int it = 0; it < KCL; it++) {
        // A: argmax over 1936 smem partials (two-level shuffle tree)
        {
            float bv = -1.0f; int bi = 0x7fffffff;
            for (int i = tid; i < NPART; i += 512) better(s_pv[i], s_pi[i], bv, bi);
            #pragma unroll
            for (int off = 16; off; off >>= 1) {
                float ov = __shfl_down_sync(0xffffffffu, bv, off);
                int   oi = __shfl_down_sync(0xffffffffu, bi, off);
                better(ov, oi, bv, bi);
            }
            if (lane == 0) { s_rv[warp] = bv; s_ri[warp] = bi; }
        }
        __syncthreads();
        if (warp == 0) {
            float bv = (lane < 16) ? s_rv[lane] : -1.0f;
            int   bi = (lane < 16) ? s_ri[lane] : 0x7fffffff;
            #pragma unroll
            for (int off = 8; off; off >>= 1) {
                float ov = __shfl_down_sync(0xffffffffu, bv, off);
                int   oi = __shfl_down_sync(0xffffffffu, bi, off);
                better(ov, oi, bv, bi);
            }
            if (lane == 0) { s_r = bi / AW; s_c = bi % AW; }
        }
        __syncthreads();
        const int r = s_r, c = s_c;
        const int r0c = max(0, r - 4), r1c = min(AW - 1, r + 4);

        if (warp == 0) {
            // B: window max on warp 0 (value = orig unless covered earlier)
            float v = -1.0f;
            if (lane < 25) {
                int y = r + lane / 5, x = c + lane % 5;
                v = src[y * H + x];
                for (int j = 0; j < it; j++)
                    if ((unsigned)(y - s_wr[j]) < 5u && (unsigned)(x - s_wc[j]) < 5u) v = 0.0f;
            }
            #pragma unroll
            for (int off = 16; off; off >>= 1)
                v = fmaxf(v, __shfl_down_sync(0xffffffffu, v, off));
            if (lane == 0) { s_mv[it] = v; s_wr[it] = r; s_wc[it] = c; }
        } else {
            // C (warps 1+): incremental colsum repair (<=45 entries)
            int nc = (r1c - r0c + 1) * 5;
            int idx = tid - 32;
            if (idx < nc) {
                int rr = r0c + idx / 5, cc = c + idx % 5;
                float s = 0.0f;
                #pragma unroll
                for (int d = 0; d < 5; d++) {
                    int y = rr + d;
                    float v = src[y * H + cc];
                    if ((unsigned)(y - r) < 5u && (unsigned)(cc - c) < 5u) v = 0.0f;
                    for (int j = 0; j < it; j++)
                        if ((unsigned)(y - s_wr[j]) < 5u && (unsigned)(cc - s_wc[j]) < 5u) v = 0.0f;
                    s = s + v;   // left-assoc, matches scan0 ring
                }
                cs[rr * H + cc] = s;
            }
        }
        __syncthreads();

        // D: recompute affected partials (<= 9 rows x <= 2 segs)
        {
            const int jlo = max(0, c - 4), jhi = min(AW - 1, c + 4);
            const int s0 = jlo / SEG, s1 = jhi / SEG;
            const int nsegs = s1 - s0 + 1;
            const int npairs = (r1c - r0c + 1) * nsegs;
            for (int p = warp; p < npairs; p += 16) {
                int rr = r0c + p / nsegs, sg = s0 + p % nsegs;
                const float* row = cs + rr * H;
                float bv2 = -1.0f; int bi2 = 0x7fffffff;
                for (int j = sg * SEG + lane; j < sg * SEG + SEG; j += 32) {
                    float v = row[j] + row[j + 1] + row[j + 2] + row[j + 3] + row[j + 4];
                    better(v, rr * AW + j, bv2, bi2);
                }
                #pragma unroll
                for (int off = 16; off; off >>= 1) {
                    float ov = __shfl_down_sync(0xffffffffu, bv2, off);
                    int   oi = __shfl_down_sync(0xffffffffu, bi2, off);
                    better(ov, oi, bv2, bi2);
                }
                if (lane == 0) { s_pv[rr * NSEG + sg] = bv2; s_pi[rr * NSEG + sg] = bi2; }
            }
        }
        __syncthreads();
    }

    if (tid < KCL) {
        g_wr[b * KCL + tid] = s_wr[tid];
        g_wc[b * KCL + tid] = s_wc[tid];
        g_mv[b * KCL + tid] = s_mv[tid];
    }
}

// ---------------------------------------------------------------------------
// eq: first-occurrence scan, grid (NB, 8) x 256 — full chip. Branchless
// exact-bit filter, 4-way unrolled loads for MLP. Global atomicMin.
// ---------------------------------------------------------------------------
__global__ __launch_bounds__(256)
void eq_kernel(const float* __restrict__ in) {
    const int b = blockIdx.x, cb = blockIdx.y, tid = threadIdx.x;

    __shared__ unsigned s_p[KCL];
    __shared__ int      s_wr[KCL], s_wc[KCL];

    if (tid < KCL) {
        s_p[tid]  = __float_as_uint(g_mv[b * KCL + tid]);
        s_wr[tid] = g_wr[b * KCL + tid];
        s_wc[tid] = g_wc[b * KCL + tid];
    }
    __syncthreads();
    const unsigned p0 = s_p[0], p1 = s_p[1], p2 = s_p[2],
                   p3 = s_p[3], p4 = s_p[4], p5 = s_p[5];

    const uint4* h4 = (const uint4*)(in + (size_t)b * H * H);
    const int b0 = cb * CE4, e0 = min(NE4, b0 + CE4);

    for (int tt = b0 + tid; tt < e0; tt += 256 * 4) {
        uint4 v[4];
        bool ok[4];
        #pragma unroll
        for (int q = 0; q < 4; q++) {
            int idx = tt + q * 256;
            ok[q] = idx < e0;
            v[q] = ok[q] ? h4[idx] : make_uint4(0u, 0u, 0u, 0u);
        }
        bool hit = false;
        #pragma unroll
        for (int q = 0; q < 4; q++) {
            hit = hit |
                (v[q].x == p0) | (v[q].y == p0) | (v[q].z == p0) | (v[q].w == p0) |
                (v[q].x == p1) | (v[q].y == p1) | (v[q].z == p1) | (v[q].w == p1) |
                (v[q].x == p2) | (v[q].y == p2) | (v[q].z == p2) | (v[q].w == p2) |
                (v[q].x == p3) | (v[q].y == p3) | (v[q].z == p3) | (v[q].w == p3) |
                (v[q].x == p4) | (v[q].y == p4) | (v[q].z == p4) | (v[q].w == p4) |
                (v[q].x == p5) | (v[q].y == p5) | (v[q].z == p5) | (v[q].w == p5);
        }
        if (!hit) continue;   // taken almost never (exact-bit matches only)
        #pragma unroll
        for (int q = 0; q < 4; q++) {
            if (!ok[q]) continue;
            #pragma unroll
            for (int u = 0; u < 4; u++) {
                unsigned val = (u == 0) ? v[q].x : (u == 1) ? v[q].y
                             : (u == 2) ? v[q].z : v[q].w;
                int id = (tt + q * 256) * 4 + u;
                #pragma unroll
                for (int i = 0; i < KCL; i++) {
                    unsigned pp = (i == 0) ? p0 : (i == 1) ? p1 : (i == 2) ? p2
                                : (i == 3) ? p3 : (i == 4) ? p4 : p5;
                    if (val == pp) {
                        int y = id / H, x = id - y * H;
                        bool cov = false;
                        for (int j = 0; j < i; j++)
                            if ((unsigned)(y - s_wr[j]) < 5u && (unsigned)(x - s_wc[j]) < 5u) cov = true;
                        if (!cov) atomicMin(&g_eq[b * KCL + i], id);
                    }
                }
            }
        }
    }
}

// ---------------------------------------------------------------------------
// refine: 10 mean-shift iterations, 5 warps/cluster. Fast-math weight
// (rsqrtf + __fdividef), x-invariants hoisted, eps-clamp hoisted out of the
// min chain (exact identity: min_k max(a_k,eps) == max(min_k a_k, eps)).
// Centers updated by 6 threads only (2 barriers/iter) — kills the
// 12k-MUFU/iter redundant-divide hotspot. Then round + 4x4 confidences.
// ---------------------------------------------------------------------------
__global__ __launch_bounds__(1024)
void refine_kernel(const float* __restrict__ in, float* __restrict__ out) {
    const int b = blockIdx.x, tid = threadIdx.x;
    const int warp = tid >> 5, lane = tid & 31;
    const float* src = in + (size_t)b * H * H;

    __shared__ float pY[KCL][RW], pX[KCL][RW], pW[KCL][RW];
    __shared__ float s_cy[KCL], s_cx[KCL];

    if (tid < KCL) {
        int fh = g_eq[b * KCL + tid];
        s_cy[tid] = (float)(fh / H);
        s_cx[tid] = (float)(fh % H);
    }
    __syncthreads();

    const int k = warp / RW;            // 0..5 for warps 0..29; warps 30,31 idle
    const int sw = warp - k * RW;
    const bool active = (warp < KCL * RW);

    for (int it = 0; it < ITERS; it++) {
        if (active) {
            // all 6 centers -> registers (constant smem indices, no spill)
            float rcy[KCL], rcx[KCL];
            #pragma unroll
            for (int i = 0; i < KCL; i++) { rcy[i] = s_cy[i]; rcx[i] = s_cx[i]; }

            float cy = rcy[0], cx = rcx[0];
            if (k == 1) { cy = rcy[1]; cx = rcx[1]; }
            if (k == 2) { cy = rcy[2]; cx = rcx[2]; }
            if (k == 3) { cy = rcy[3]; cx = rcx[3]; }
            if (k == 4) { cy = rcy[4]; cx = rcx[4]; }
            if (k == 5) { cy = rcy[5]; cx = rcx[5]; }

            const int y0 = max(0, (int)floorf(cy - 12.0f));
            const int y1 = min(H - 1, (int)ceilf(cy + 12.0f));
            const int x0 = max(0, (int)floorf(cx - 12.0f));
            const int x1 = min(H - 1, (int)ceilf(cx + 12.0f));
            const int w  = x1 - x0 + 1;        // <= 26 <= 32 lanes

            float sy = 0.0f, sx = 0.0f, swt = 0.0f;
            const int x = x0 + lane;
            if (lane < w) {
                const float fx = (float)x;
                const float dx2 = (fx - cx) * (fx - cx);
                // x-invariants for the min-distance loop
                float ex2[KCL];
                #pragma unroll
                for (int i = 0; i < KCL; i++) {
                    float ex = fx - rcx[i];
                    ex2[i] = ex * ex;
                }
                for (int y = y0 + sw; y <= y1; y += RW) {
                    const float fy = (float)y;
                    const float dy = fy - cy;
                    const float d2r = fmaf(dy, dy, dx2);
                    if (d2r < 144.0f) {
                        // min over raw squared distances, eps-clamp hoisted
                        float mr = d2r;
                        #pragma unroll
                        for (int k2 = 0; k2 < KCL; k2++) {
                            float ey = fy - rcy[k2];
                            mr = fminf(mr, fmaf(ey, ey, ex2[k2]));
                        }
                        const float d2 = fmaxf(d2r, 1e-6f);
                        const float m2 = fmaxf(mr,  1e-6f);
                        float s = m2 * rsqrtf(m2);               // ~sqrt(m2)
                        float wgt = __fdividef(src[y * H + x] * s, d2);
                        sy = fmaf(wgt, fy, sy);
                        sx = fmaf(wgt, fx, sx);
                        swt += wgt;
                    }
                }
            }
            #pragma unroll
            for (int off = 16; off; off >>= 1) {
                sy  += __shfl_down_sync(0xffffffffu, sy, off);
                sx  += __shfl_down_sync(0xffffffffu, sx, off);
                swt += __shfl_down_sync(0xffffffffu, swt, off);
            }
            if (lane == 0) { pY[k][sw] = sy; pX[k][sw] = sx; pW[k][sw] = swt; }
        }
        __syncthreads();
        // 6 threads update centers (12 MUFU total per iteration)
        if (tid < KCL) {
            float ay = pY[tid][0] + pY[tid][1] + pY[tid][2] + pY[tid][3] + pY[tid][4];
            float ax = pX[tid][0] + pX[tid][1] + pX[tid][2] + pX[tid][3] + pX[tid][4];
            float aw = pW[tid][0] + pW[tid][1] + pW[tid][2] + pW[tid][3] + pW[tid][4];
            s_cy[tid] = __fdividef(ay, aw);
            s_cx[tid] = __fdividef(ax, aw);
        }
        __syncthreads();
    }

    if (tid < KCL) {
        float fy = s_cy[tid], fx = s_cx[tid];
        int iy = (int)rintf(fy);   // round-half-to-even == jnp.round
        int ix = (int)rintf(fx);
        out[(b * KCL + tid) * 2 + 0] = (float)iy;
        out[(b * KCL + tid) * 2 + 1] = (float)ix;
        int sy0 = min(max(iy - 2, 0), H - 4);   // dynamic_slice clamp
        int sx0 = min(max(ix - 2, 0), H - 4);
        float cf = 0.0f;
        #pragma unroll
        for (int di = 0; di < 4; di++)
            #pragma unroll
            for (int dj = 0; dj < 4; dj++)
                cf += src[(sy0 + di) * H + (sx0 + dj)];
        out[NB * KCL * 2 + b * KCL + tid] = cf;
    }
}

extern "C" void kernel_launch(void* const* d_in, const int* in_sizes, int n_in,
                              void* d_out, int out_size) {
    const float* hm = (const float*)d_in[0];
    float* out = (float*)d_out;

    scan0_kernel<<<dim3(NB, NCH0), 128>>>(hm);
    greedy6_kernel<<<NB, 512>>>(hm);
    eq_kernel<<<dim3(NB, NCHE), 256>>>(hm);
    refine_kernel<<<NB, 1024>>>(hm, out);
}